// round 2
// baseline (speedup 1.0000x reference)
#include <cuda_runtime.h>
#include <math.h>

// Problem constants (from reference)
#define B_   2
#define L_   2048
#define D_   1024
#define N_   16
#define R_   64
#define M_   (B_ * L_)        // 4096 rows
#define DBC_ (R_ + 2 * N_)    // 96
#define LC   64               // chunk length
#define NC   (L_ / LC)        // 32 chunks
#define CH   (B_ * D_)        // 2048 channels

// Scratch (no cudaMalloc allowed -> __device__ globals)
__device__ float g_dbc[M_ * DBC_];      // [M, 96]  : delta_low | Bm | Cm
__device__ float g_delta[M_ * D_];      // [M, D]   : softplus(delta_low @ Wup^T + b)
__device__ float g_S[NC * CH];          // per-chunk sum of delta
__device__ float g_hend[NC * CH * N_];  // local chunk-end state (h_in = 0)
__device__ float g_hin[NC * CH * N_];   // corrected chunk-entry state

// ---------------------------------------------------------------------------
// GEMM1: g_dbc[m, j] = sum_k x[m,k] * W_dbc[j,k] + b_dbc[j]
// Tile 32(M) x 96(N) x 64(K), 256 threads (16x16), 2x6 per thread.
// 128 CTAs -> covers 148 SMs far better than the old 64-CTA shape.
// ---------------------------------------------------------------------------
__global__ __launch_bounds__(256) void k_gemm_dbc(const float* __restrict__ X,
                                                  const float* __restrict__ W,
                                                  const float* __restrict__ bias) {
    __shared__ float Xs[64][33];  // [k][m]  (stride 33: conflict-free STS)
    __shared__ float Ws[64][97];  // [k][j]  (stride 97: conflict-free STS)
    const int tid = threadIdx.x;
    const int m0  = blockIdx.x * 32;
    const int ty  = tid >> 4;     // 0..15 -> 2 rows each
    const int tx  = tid & 15;     // 0..15 -> 6 cols each

    float acc[2][6];
#pragma unroll
    for (int i = 0; i < 2; i++)
#pragma unroll
        for (int j = 0; j < 6; j++) acc[i][j] = 0.f;

    for (int k0 = 0; k0 < 1024; k0 += 64) {
#pragma unroll
        for (int i = 0; i < 8; i++) {            // 32x64 X tile (2048 elems)
            int idx = tid + i * 256;
            int m = idx >> 6, kk = idx & 63;
            Xs[kk][m] = X[(m0 + m) * 1024 + k0 + kk];
        }
#pragma unroll
        for (int i = 0; i < 24; i++) {           // 96x64 W tile (6144 elems)
            int idx = tid + i * 256;
            int j = idx >> 6, kk = idx & 63;
            Ws[kk][j] = W[j * 1024 + k0 + kk];
        }
        __syncthreads();
#pragma unroll 8
        for (int kk = 0; kk < 64; kk++) {
            float rm[2], rn[6];
#pragma unroll
            for (int i = 0; i < 2; i++) rm[i] = Xs[kk][ty * 2 + i];
#pragma unroll
            for (int j = 0; j < 6; j++) rn[j] = Ws[kk][tx * 6 + j];
#pragma unroll
            for (int i = 0; i < 2; i++)
#pragma unroll
                for (int j = 0; j < 6; j++) acc[i][j] = fmaf(rm[i], rn[j], acc[i][j]);
        }
        __syncthreads();
    }
#pragma unroll
    for (int i = 0; i < 2; i++)
#pragma unroll
        for (int j = 0; j < 6; j++) {
            int col = tx * 6 + j;
            g_dbc[(m0 + ty * 2 + i) * DBC_ + col] = acc[i][j] + bias[col];
        }
}

// ---------------------------------------------------------------------------
// GEMM2: g_delta[m, d] = softplus( sum_r g_dbc[m, r] * Wup[d, r] + bup[d] )
// Tile 64(M) x 64(D) x 64(K=R), 256 threads, 4x4 per thread. 1024 CTAs.
// ---------------------------------------------------------------------------
__global__ __launch_bounds__(256) void k_gemm_delta(const float* __restrict__ Wup,
                                                    const float* __restrict__ bup) {
    __shared__ float Ls[64][65];  // [r][m]
    __shared__ float Ws[64][65];  // [r][d]
    const int tid = threadIdx.x;
    const int m0 = blockIdx.x * 64;
    const int d0 = blockIdx.y * 64;

#pragma unroll
    for (int i = 0; i < 16; i++) {
        int idx = tid + i * 256;          // 0..4095
        int a = idx >> 6, rr = idx & 63;  // a: row index (m or d)
        Ls[rr][a] = g_dbc[(m0 + a) * DBC_ + rr];
        Ws[rr][a] = Wup[(d0 + a) * R_ + rr];
    }
    __syncthreads();

    const int ty = tid >> 4, tx = tid & 15;
    float acc[4][4];
#pragma unroll
    for (int i = 0; i < 4; i++)
#pragma unroll
        for (int j = 0; j < 4; j++) acc[i][j] = 0.f;

#pragma unroll 8
    for (int r = 0; r < 64; r++) {
        float rm[4], rn[4];
#pragma unroll
        for (int i = 0; i < 4; i++) rm[i] = Ls[r][ty * 4 + i];
#pragma unroll
        for (int j = 0; j < 4; j++) rn[j] = Ws[r][tx * 4 + j];
#pragma unroll
        for (int i = 0; i < 4; i++)
#pragma unroll
            for (int j = 0; j < 4; j++) acc[i][j] = fmaf(rm[i], rn[j], acc[i][j]);
    }
#pragma unroll
    for (int i = 0; i < 4; i++)
#pragma unroll
        for (int j = 0; j < 4; j++) {
            int dd = d0 + tx * 4 + j;
            float v = acc[i][j] + bup[dd];
            float sp = (v > 20.f) ? v : log1pf(__expf(v));  // softplus
            g_delta[(m0 + ty * 4 + i) * D_ + dd] = sp;
        }
}

// ---------------------------------------------------------------------------
// Helper: load A row, detect A_n == A_0*(n+1) (true for the reference setup:
// A = -exp(log(arange(1..16)))), enabling 1 exp + power-chain per timestep.
// ---------------------------------------------------------------------------
__device__ __forceinline__ bool load_A(const float* __restrict__ A_log, int d,
                                       float Av[16]) {
    const float4* p = (const float4*)(A_log + d * N_);
    float4 a0 = p[0], a1 = p[1], a2 = p[2], a3 = p[3];
    Av[0] = -__expf(a0.x);  Av[1] = -__expf(a0.y);
    Av[2] = -__expf(a0.z);  Av[3] = -__expf(a0.w);
    Av[4] = -__expf(a1.x);  Av[5] = -__expf(a1.y);
    Av[6] = -__expf(a1.z);  Av[7] = -__expf(a1.w);
    Av[8] = -__expf(a2.x);  Av[9] = -__expf(a2.y);
    Av[10] = -__expf(a2.z); Av[11] = -__expf(a2.w);
    Av[12] = -__expf(a3.x); Av[13] = -__expf(a3.y);
    Av[14] = -__expf(a3.z); Av[15] = -__expf(a3.w);
    bool fast = true;
#pragma unroll
    for (int n = 1; n < 16; n++) {
        float tgt = Av[0] * (float)(n + 1);
        if (fabsf(Av[n] - tgt) > 1e-4f + 1e-5f * fabsf(tgt)) fast = false;
    }
    return fast;
}

__device__ __forceinline__ void load16(const float* __restrict__ p, float v[16]) {
    float4 b0 = *(const float4*)(p);
    float4 b1 = *(const float4*)(p + 4);
    float4 b2 = *(const float4*)(p + 8);
    float4 b3 = *(const float4*)(p + 12);
    v[0] = b0.x;  v[1] = b0.y;  v[2] = b0.z;  v[3] = b0.w;
    v[4] = b1.x;  v[5] = b1.y;  v[6] = b1.z;  v[7] = b1.w;
    v[8] = b2.x;  v[9] = b2.y;  v[10] = b2.z; v[11] = b2.w;
    v[12] = b3.x; v[13] = b3.y; v[14] = b3.z; v[15] = b3.w;
}

// ---------------------------------------------------------------------------
// Phase A: per (chunk, b, d) local scan with h_in = 0.
// Writes chunk-end state and sum(delta) over chunk (transfer = exp(A_n * S)).
// ---------------------------------------------------------------------------
__global__ __launch_bounds__(256) void k_scanA(const float* __restrict__ x,
                                               const float* __restrict__ A_log) {
    const int g = blockIdx.x * 256 + threadIdx.x;   // 65536 threads
    const int d = g & (D_ - 1);
    const int rest = g >> 10;
    const int b = rest & (B_ - 1);
    const int c = rest >> 1;

    float Av[16];
    const bool fast = load_A(A_log, d, Av);
    const float A0 = Av[0];

    float h[16];
#pragma unroll
    for (int n = 0; n < 16; n++) h[n] = 0.f;
    float S = 0.f;

    const int trow0 = b * L_ + c * LC;
    const float* dptr = g_delta + trow0 * D_ + d;
    const float* xptr = x + trow0 * D_ + d;

    for (int tt = 0; tt < LC; tt++) {
        float dt = dptr[tt * D_];
        float xt = xptr[tt * D_];
        S += dt;
        float dx = dt * xt;
        float bm[16];
        load16(g_dbc + (trow0 + tt) * DBC_ + R_, bm);  // Bm (warp-broadcast)
        if (fast) {
            float p = __expf(dt * A0);
            float a = p;
#pragma unroll
            for (int n = 0; n < 16; n++) { h[n] = fmaf(a, h[n], dx * bm[n]); a *= p; }
        } else {
#pragma unroll
            for (int n = 0; n < 16; n++)
                h[n] = fmaf(__expf(dt * Av[n]), h[n], dx * bm[n]);
        }
    }

    const int ch = b * D_ + d;
    float* hp = g_hend + (c * CH + ch) * N_;
    *(float4*)(hp)      = make_float4(h[0], h[1], h[2], h[3]);
    *(float4*)(hp + 4)  = make_float4(h[4], h[5], h[6], h[7]);
    *(float4*)(hp + 8)  = make_float4(h[8], h[9], h[10], h[11]);
    *(float4*)(hp + 12) = make_float4(h[12], h[13], h[14], h[15]);
    g_S[c * CH + ch] = S;
}

// ---------------------------------------------------------------------------
// Phase B: sequential combine across 32 chunks per (channel, n).
// h_in(c+1) = exp(A_n * S_c) * h_in(c) + h_end_local(c)
// ---------------------------------------------------------------------------
__global__ __launch_bounds__(256) void k_scanB(const float* __restrict__ A_log) {
    const int g = blockIdx.x * 256 + threadIdx.x;   // 32768 threads
    const int n = g & (N_ - 1);
    const int ch = g >> 4;
    const int d = ch & (D_ - 1);
    const float An = -__expf(A_log[d * N_ + n]);

    float h = 0.f;
#pragma unroll 4
    for (int c = 0; c < NC; c++) {
        int idx = (c * CH + ch) * N_ + n;
        g_hin[idx] = h;
        h = fmaf(__expf(An * g_S[c * CH + ch]), h, g_hend[idx]);
    }
}

// ---------------------------------------------------------------------------
// Phase C: replay each chunk from corrected h_in, emit y_t = sum_n h_n * C_n.
// ---------------------------------------------------------------------------
__global__ __launch_bounds__(256) void k_scanC(const float* __restrict__ x,
                                               const float* __restrict__ A_log,
                                               float* __restrict__ y) {
    const int g = blockIdx.x * 256 + threadIdx.x;   // 65536 threads
    const int d = g & (D_ - 1);
    const int rest = g >> 10;
    const int b = rest & (B_ - 1);
    const int c = rest >> 1;

    float Av[16];
    const bool fast = load_A(A_log, d, Av);
    const float A0 = Av[0];

    const int ch = b * D_ + d;
    float h[16];
    load16(g_hin + (c * CH + ch) * N_, h);

    const int trow0 = b * L_ + c * LC;
    const float* dptr = g_delta + trow0 * D_ + d;
    const float* xptr = x + trow0 * D_ + d;
    float* yptr = y + trow0 * D_ + d;

    for (int tt = 0; tt < LC; tt++) {
        float dt = dptr[tt * D_];
        float xt = xptr[tt * D_];
        float dx = dt * xt;
        const float* row = g_dbc + (trow0 + tt) * DBC_;
        float bm[16], cm[16];
        load16(row + R_, bm);        // Bm
        load16(row + R_ + N_, cm);   // Cm
        float acc = 0.f;
        if (fast) {
            float p = __expf(dt * A0);
            float a = p;
#pragma unroll
            for (int n = 0; n < 16; n++) {
                h[n] = fmaf(a, h[n], dx * bm[n]);
                acc = fmaf(h[n], cm[n], acc);
                a *= p;
            }
        } else {
#pragma unroll
            for (int n = 0; n < 16; n++) {
                h[n] = fmaf(__expf(dt * Av[n]), h[n], dx * bm[n]);
                acc = fmaf(h[n], cm[n], acc);
            }
        }
        yptr[tt * D_] = acc;
    }
}

// ---------------------------------------------------------------------------
// Launch: dbc GEMM -> delta GEMM -> chunk scan (A) -> combine (B) -> replay (C)
// ---------------------------------------------------------------------------
extern "C" void kernel_launch(void* const* d_in, const int* in_sizes, int n_in,
                              void* d_out, int out_size) {
    const float* x     = (const float*)d_in[0];
    const float* A_log = (const float*)d_in[1];
    const float* W_dbc = (const float*)d_in[2];
    const float* b_dbc = (const float*)d_in[3];
    const float* W_up  = (const float*)d_in[4];
    const float* b_up  = (const float*)d_in[5];
    float* y = (float*)d_out;

    k_gemm_dbc<<<M_ / 32, 256>>>(x, W_dbc, b_dbc);
    k_gemm_delta<<<dim3(M_ / 64, D_ / 64), 256>>>(W_up, b_up);
    k_scanA<<<(NC * CH) / 256, 256>>>(x, A_log);
    k_scanB<<<(CH * N_) / 256, 256>>>(A_log);
    k_scanC<<<(NC * CH) / 256, 256>>>(x, A_log, y);
}